// round 3
// baseline (speedup 1.0000x reference)
#include <cuda_runtime.h>
#include <math.h>

#define BATCH 8
#define SEQ   1500
#define DMODEL 768
#define NHEAD 12
#define DHEAD 64
#define NTOK  (BATCH * SEQ)        // 12000
#define QSCALE 0.125f
#define NEG_BIG (-1e30f)

// ------------------------- scratch (device globals; no allocation) ---------
__device__ float g_q[(size_t)BATCH * NHEAD * SEQ * DHEAD];   // [b,h,s,dh], pre-scaled
__device__ float g_k[(size_t)BATCH * NHEAD * SEQ * DHEAD];
__device__ float g_v[(size_t)BATCH * NHEAD * SEQ * DHEAD];
__device__ float g_ctx[(size_t)NTOK * DMODEL];               // [b,s,d]

// ------------------------- GEMM tiling --------------------------------------
#define BM 128
#define BN 64
#define BK 16
// 256 threads, 16x16 logical grid, each thread computes 8x4 outputs.

// ===========================================================================
// Kernel 1: fused QKV projection.
//   y = x @ W^T (+bias); Q additionally scaled by QSCALE.
//   Writes q/k/v in [b,h,s,dh] layout.
//   Grid: x = 3*DMODEL/BN = 36 n-tiles, y = ceil(NTOK/BM) = 94 m-tiles.
// ===========================================================================
__global__ __launch_bounds__(256) void qkv_kernel(
    const float* __restrict__ x,
    const float* __restrict__ Wq, const float* __restrict__ bq,
    const float* __restrict__ Wk,
    const float* __restrict__ Wv, const float* __restrict__ bv)
{
    __shared__ float As[BK][BM];
    __shared__ float Bs[BK][BN];

    const int tid = threadIdx.x;
    const int tx = tid & 15;
    const int ty = tid >> 4;

    const int mBase = blockIdx.y * BM;
    const int nBase = blockIdx.x * BN;            // 0..2303
    const int mat = nBase / DMODEL;               // 0=Q,1=K,2=V
    const int oBase = nBase - mat * DMODEL;       // 0..704, multiple of 64
    const float* W = (mat == 0) ? Wq : (mat == 1) ? Wk : Wv;

    const int ldRow = tid >> 2;                   // 0..63
    const int ldCol = (tid & 3) * 4;              // 0,4,8,12
    const int r0 = mBase + ldRow;
    const int r1 = mBase + ldRow + 64;
    const bool v0 = r0 < NTOK;
    const bool v1 = r1 < NTOK;
    const float* xp0 = x + (size_t)r0 * DMODEL + ldCol;
    const float* xp1 = x + (size_t)r1 * DMODEL + ldCol;
    const float* wp  = W + (size_t)(oBase + ldRow) * DMODEL + ldCol;

    float acc[8][4];
#pragma unroll
    for (int i = 0; i < 8; i++)
#pragma unroll
        for (int j = 0; j < 4; j++) acc[i][j] = 0.f;

    for (int k0 = 0; k0 < DMODEL; k0 += BK) {
        float4 a0 = v0 ? *(const float4*)(xp0 + k0) : make_float4(0, 0, 0, 0);
        float4 a1 = v1 ? *(const float4*)(xp1 + k0) : make_float4(0, 0, 0, 0);
        float4 bb = *(const float4*)(wp + k0);
        __syncthreads();
        As[ldCol + 0][ldRow] = a0.x; As[ldCol + 1][ldRow] = a0.y;
        As[ldCol + 2][ldRow] = a0.z; As[ldCol + 3][ldRow] = a0.w;
        As[ldCol + 0][ldRow + 64] = a1.x; As[ldCol + 1][ldRow + 64] = a1.y;
        As[ldCol + 2][ldRow + 64] = a1.z; As[ldCol + 3][ldRow + 64] = a1.w;
        Bs[ldCol + 0][ldRow] = bb.x; Bs[ldCol + 1][ldRow] = bb.y;
        Bs[ldCol + 2][ldRow] = bb.z; Bs[ldCol + 3][ldRow] = bb.w;
        __syncthreads();
#pragma unroll
        for (int k = 0; k < BK; k++) {
            float4 af0 = *(const float4*)&As[k][ty * 8];
            float4 af1 = *(const float4*)&As[k][ty * 8 + 4];
            float4 bf  = *(const float4*)&Bs[k][tx * 4];
            float am[8] = {af0.x, af0.y, af0.z, af0.w, af1.x, af1.y, af1.z, af1.w};
            float bn[4] = {bf.x, bf.y, bf.z, bf.w};
#pragma unroll
            for (int i = 0; i < 8; i++)
#pragma unroll
                for (int j = 0; j < 4; j++) acc[i][j] = fmaf(am[i], bn[j], acc[i][j]);
        }
    }

    // epilogue
    float bias[4] = {0.f, 0.f, 0.f, 0.f};
    if (mat == 0) {
#pragma unroll
        for (int j = 0; j < 4; j++) bias[j] = bq[oBase + tx * 4 + j];
    } else if (mat == 2) {
#pragma unroll
        for (int j = 0; j < 4; j++) bias[j] = bv[oBase + tx * 4 + j];
    }
    float* dst = (mat == 0) ? g_q : (mat == 1) ? g_k : g_v;
    const int hh = oBase >> 6;  // head index (whole tile is one head since oBase%64==0... 64-aligned)

#pragma unroll
    for (int i = 0; i < 8; i++) {
        int t = mBase + ty * 8 + i;
        if (t >= NTOK) continue;
        int b_ = t / SEQ;
        int s_ = t - b_ * SEQ;
        float4 ov;
        float v0_ = acc[i][0] + bias[0];
        float v1_ = acc[i][1] + bias[1];
        float v2_ = acc[i][2] + bias[2];
        float v3_ = acc[i][3] + bias[3];
        if (mat == 0) { v0_ *= QSCALE; v1_ *= QSCALE; v2_ *= QSCALE; v3_ *= QSCALE; }
        ov.x = v0_; ov.y = v1_; ov.z = v2_; ov.w = v3_;
        size_t idx = (((size_t)b_ * NHEAD + hh) * SEQ + s_) * DHEAD + tx * 4;
        *(float4*)&dst[idx] = ov;
    }
}

// ===========================================================================
// Kernel 2: flash attention, fp32.
//   Grid: x = ceil(SEQ/64)=24 q-tiles, y = BATCH*NHEAD = 96.
//   Block 256 threads (16x16); thread owns 4 q-rows (ty) x 4 cols (tx).
//   smem: Qt[d][m], KP[d][n] (reused as P[m][j]), Vs[j][d] — 48 KB total.
// ===========================================================================
__global__ __launch_bounds__(256) void attn_kernel()
{
    __shared__ float Qt[64][64];   // [d][m]   (Q transposed)
    __shared__ float KP[64][64];   // [d][n] for K^T, then [m][j] for P
    __shared__ float Vs[64][64];   // [j][d]

    const int tid = threadIdx.x;
    const int tx = tid & 15;
    const int ty = tid >> 4;
    const int bh = blockIdx.y;
    const int b_ = bh / NHEAD;
    const int h_ = bh - b_ * NHEAD;
    const int q0 = blockIdx.x * 64;

    const float* Qg = g_q + (size_t)bh * SEQ * DHEAD;
    const float* Kg = g_k + (size_t)bh * SEQ * DHEAD;
    const float* Vg = g_v + (size_t)bh * SEQ * DHEAD;

    const int ldRow = tid >> 2;            // 0..63
    const int ldC0  = (tid & 3) * 4;       // 0,4,8,12

    // ---- load Q tile, transposed into Qt[d][m] ----
    {
        int qr = q0 + ldRow;
        const float* qp = Qg + (size_t)qr * DHEAD;
#pragma unroll
        for (int p = 0; p < 4; p++) {
            int c = ldC0 + p * 16;
            float4 qv = (qr < SEQ) ? *(const float4*)(qp + c) : make_float4(0, 0, 0, 0);
            Qt[c + 0][ldRow] = qv.x; Qt[c + 1][ldRow] = qv.y;
            Qt[c + 2][ldRow] = qv.z; Qt[c + 3][ldRow] = qv.w;
        }
    }

    float O[4][4];
#pragma unroll
    for (int i = 0; i < 4; i++)
#pragma unroll
        for (int j = 0; j < 4; j++) O[i][j] = 0.f;
    float mrow[4] = {NEG_BIG, NEG_BIG, NEG_BIG, NEG_BIG};
    float lrow[4] = {0.f, 0.f, 0.f, 0.f};

    const int NKT = (SEQ + 63) / 64;  // 24
    for (int kt = 0; kt < NKT; kt++) {
        const int kBase = kt * 64;

        // stage K/V tile in registers (overlap gmem latency with prior compute)
        float4 kfr[4], vfr[4];
        {
            int kr = kBase + ldRow;
            bool ok = kr < SEQ;
            const float* kp = Kg + (size_t)kr * DHEAD;
            const float* vp = Vg + (size_t)kr * DHEAD;
#pragma unroll
            for (int p = 0; p < 4; p++) {
                int c = ldC0 + p * 16;
                kfr[p] = ok ? *(const float4*)(kp + c) : make_float4(0, 0, 0, 0);
                vfr[p] = ok ? *(const float4*)(vp + c) : make_float4(0, 0, 0, 0);
            }
        }
        __syncthreads();  // prior P/V consumers done
#pragma unroll
        for (int p = 0; p < 4; p++) {
            int c = ldC0 + p * 16;
            KP[c + 0][ldRow] = kfr[p].x; KP[c + 1][ldRow] = kfr[p].y;
            KP[c + 2][ldRow] = kfr[p].z; KP[c + 3][ldRow] = kfr[p].w;
            *(float4*)&Vs[ldRow][c] = vfr[p];
        }
        __syncthreads();

        // ---- S = Q @ K^T (regs 4x4 per thread) ----
        float s[4][4];
#pragma unroll
        for (int i = 0; i < 4; i++)
#pragma unroll
            for (int j = 0; j < 4; j++) s[i][j] = 0.f;
#pragma unroll 8
        for (int d = 0; d < DHEAD; d++) {
            float4 af = *(const float4*)&Qt[d][ty * 4];
            float4 bf = *(const float4*)&KP[d][tx * 4];
            float am[4] = {af.x, af.y, af.z, af.w};
            float bn[4] = {bf.x, bf.y, bf.z, bf.w};
#pragma unroll
            for (int i = 0; i < 4; i++)
#pragma unroll
                for (int j = 0; j < 4; j++) s[i][j] = fmaf(am[i], bn[j], s[i][j]);
        }

        // ---- mask invalid k columns ----
#pragma unroll
        for (int j = 0; j < 4; j++) {
            if (kBase + tx * 4 + j >= SEQ) {
#pragma unroll
                for (int i = 0; i < 4; i++) s[i][j] = NEG_BIG;
            }
        }

        // ---- online softmax update ----
        float alpha[4];
#pragma unroll
        for (int i = 0; i < 4; i++) {
            float mx = fmaxf(fmaxf(s[i][0], s[i][1]), fmaxf(s[i][2], s[i][3]));
            mx = fmaxf(mx, __shfl_xor_sync(0xffffffffu, mx, 1));
            mx = fmaxf(mx, __shfl_xor_sync(0xffffffffu, mx, 2));
            mx = fmaxf(mx, __shfl_xor_sync(0xffffffffu, mx, 4));
            mx = fmaxf(mx, __shfl_xor_sync(0xffffffffu, mx, 8));
            float mnew = fmaxf(mrow[i], mx);
            alpha[i] = __expf(mrow[i] - mnew);
            mrow[i] = mnew;
            float rs = 0.f;
#pragma unroll
            for (int j = 0; j < 4; j++) {
                s[i][j] = __expf(s[i][j] - mnew);
                rs += s[i][j];
            }
            rs += __shfl_xor_sync(0xffffffffu, rs, 1);
            rs += __shfl_xor_sync(0xffffffffu, rs, 2);
            rs += __shfl_xor_sync(0xffffffffu, rs, 4);
            rs += __shfl_xor_sync(0xffffffffu, rs, 8);
            lrow[i] = lrow[i] * alpha[i] + rs;
#pragma unroll
            for (int j = 0; j < 4; j++) O[i][j] *= alpha[i];
        }

        __syncthreads();  // everyone done reading K^T from KP
        // ---- write P into KP as [m][j] ----
#pragma unroll
        for (int i = 0; i < 4; i++) {
            float4 pv = make_float4(s[i][0], s[i][1], s[i][2], s[i][3]);
            *(float4*)&KP[ty * 4 + i][tx * 4] = pv;
        }
        __syncthreads();

        // ---- O += P @ V ----
#pragma unroll 8
        for (int j = 0; j < 64; j++) {
            float4 vv = *(const float4*)&Vs[j][tx * 4];
#pragma unroll
            for (int i = 0; i < 4; i++) {
                float p = KP[ty * 4 + i][j];
                O[i][0] = fmaf(p, vv.x, O[i][0]);
                O[i][1] = fmaf(p, vv.y, O[i][1]);
                O[i][2] = fmaf(p, vv.z, O[i][2]);
                O[i][3] = fmaf(p, vv.w, O[i][3]);
            }
        }
    }

    // ---- finalize: ctx[b, s, h*64 + dh] = O / l ----
#pragma unroll
    for (int i = 0; i < 4; i++) {
        int qr = q0 + ty * 4 + i;
        if (qr >= SEQ) continue;
        float inv = 1.f / lrow[i];
        float4 ov = make_float4(O[i][0] * inv, O[i][1] * inv, O[i][2] * inv, O[i][3] * inv);
        size_t idx = ((size_t)b_ * SEQ + qr) * DMODEL + h_ * DHEAD + tx * 4;
        *(float4*)&g_ctx[idx] = ov;
    }
}

// ===========================================================================
// Kernel 3: output projection.  out = ctx @ Wo^T + bo
//   Grid: x = DMODEL/BN = 12 n-tiles, y = 94 m-tiles.
// ===========================================================================
__global__ __launch_bounds__(256) void out_kernel(
    const float* __restrict__ Wo, const float* __restrict__ bo,
    float* __restrict__ out)
{
    __shared__ float As[BK][BM];
    __shared__ float Bs[BK][BN];

    const int tid = threadIdx.x;
    const int tx = tid & 15;
    const int ty = tid >> 4;

    const int mBase = blockIdx.y * BM;
    const int oBase = blockIdx.x * BN;

    const int ldRow = tid >> 2;
    const int ldCol = (tid & 3) * 4;
    const int r0 = mBase + ldRow;
    const int r1 = mBase + ldRow + 64;
    const bool v0 = r0 < NTOK;
    const bool v1 = r1 < NTOK;
    const float* xp0 = g_ctx + (size_t)r0 * DMODEL + ldCol;
    const float* xp1 = g_ctx + (size_t)r1 * DMODEL + ldCol;
    const float* wp  = Wo + (size_t)(oBase + ldRow) * DMODEL + ldCol;

    float acc[8][4];
#pragma unroll
    for (int i = 0; i < 8; i++)
#pragma unroll
        for (int j = 0; j < 4; j++) acc[i][j] = 0.f;

    for (int k0 = 0; k0 < DMODEL; k0 += BK) {
        float4 a0 = v0 ? *(const float4*)(xp0 + k0) : make_float4(0, 0, 0, 0);
        float4 a1 = v1 ? *(const float4*)(xp1 + k0) : make_float4(0, 0, 0, 0);
        float4 bb = *(const float4*)(wp + k0);
        __syncthreads();
        As[ldCol + 0][ldRow] = a0.x; As[ldCol + 1][ldRow] = a0.y;
        As[ldCol + 2][ldRow] = a0.z; As[ldCol + 3][ldRow] = a0.w;
        As[ldCol + 0][ldRow + 64] = a1.x; As[ldCol + 1][ldRow + 64] = a1.y;
        As[ldCol + 2][ldRow + 64] = a1.z; As[ldCol + 3][ldRow + 64] = a1.w;
        Bs[ldCol + 0][ldRow] = bb.x; Bs[ldCol + 1][ldRow] = bb.y;
        Bs[ldCol + 2][ldRow] = bb.z; Bs[ldCol + 3][ldRow] = bb.w;
        __syncthreads();
#pragma unroll
        for (int k = 0; k < BK; k++) {
            float4 af0 = *(const float4*)&As[k][ty * 8];
            float4 af1 = *(const float4*)&As[k][ty * 8 + 4];
            float4 bf  = *(const float4*)&Bs[k][tx * 4];
            float am[8] = {af0.x, af0.y, af0.z, af0.w, af1.x, af1.y, af1.z, af1.w};
            float bn[4] = {bf.x, bf.y, bf.z, bf.w};
#pragma unroll
            for (int i = 0; i < 8; i++)
#pragma unroll
                for (int j = 0; j < 4; j++) acc[i][j] = fmaf(am[i], bn[j], acc[i][j]);
        }
    }

    float4 bias = *(const float4*)&bo[oBase + tx * 4];
#pragma unroll
    for (int i = 0; i < 8; i++) {
        int t = mBase + ty * 8 + i;
        if (t >= NTOK) continue;
        float4 ov = make_float4(acc[i][0] + bias.x, acc[i][1] + bias.y,
                                acc[i][2] + bias.z, acc[i][3] + bias.w);
        *(float4*)&out[(size_t)t * DMODEL + oBase + tx * 4] = ov;
    }
}

// ===========================================================================
extern "C" void kernel_launch(void* const* d_in, const int* in_sizes, int n_in,
                              void* d_out, int out_size)
{
    const float* x  = (const float*)d_in[0];
    const float* Wq = (const float*)d_in[1];
    const float* bq = (const float*)d_in[2];
    const float* Wk = (const float*)d_in[3];
    const float* Wv = (const float*)d_in[4];
    const float* bv = (const float*)d_in[5];
    const float* Wo = (const float*)d_in[6];
    const float* bo = (const float*)d_in[7];
    float* out = (float*)d_out;

    dim3 gQKV(3 * DMODEL / BN, (NTOK + BM - 1) / BM);   // (36, 94)
    qkv_kernel<<<gQKV, 256>>>(x, Wq, bq, Wk, Wv, bv);

    dim3 gAtt((SEQ + 63) / 64, BATCH * NHEAD);          // (24, 96)
    attn_kernel<<<gAtt, 256>>>();

    dim3 gOut(DMODEL / BN, (NTOK + BM - 1) / BM);       // (12, 94)
    out_kernel<<<gOut, 256>>>(Wo, bo, out);
}